// round 4
// baseline (speedup 1.0000x reference)
#include <cuda_runtime.h>

#define NB   32
#define CCH  192
#define HW   112
#define IMG  (HW*HW)
#define NHW_F ((float)(NB*IMG))
#define BN_EPS 1e-5f
#define STRIP 16              // output rows per warp (7 warps x 16 = 112)

typedef unsigned long long u64;

// Scratch for channel statistics / folded affine params (no cudaMalloc allowed)
__device__ float g_sum[CCH];      // sum of raw conv (no bias)
__device__ float g_sumsq[CCH];    // sum of raw conv^2
__device__ float g_scale[CCH];
__device__ float g_shift[CCH];

__global__ void zero_stats_kernel() {
    int i = threadIdx.x;
    if (i < CCH) { g_sum[i] = 0.f; g_sumsq[i] = 0.f; }
}

// ---- packed f32x2 helpers (Blackwell sm_103a) ----
__device__ __forceinline__ u64 pk(float lo, float hi) {
    u64 r; asm("mov.b64 %0, {%1, %2};" : "=l"(r) : "f"(lo), "f"(hi)); return r;
}
__device__ __forceinline__ void upk(u64 v, float& lo, float& hi) {
    asm("mov.b64 {%0, %1}, %2;" : "=f"(lo), "=f"(hi) : "l"(v));
}
__device__ __forceinline__ u64 fma2(u64 a, u64 b, u64 c) {
    u64 d; asm("fma.rn.f32x2 %0, %1, %2, %3;" : "=l"(d) : "l"(a), "l"(b), "l"(c)); return d;
}
__device__ __forceinline__ u64 mul2(u64 a, u64 b) {
    u64 d; asm("mul.rn.f32x2 %0, %1, %2;" : "=l"(d) : "l"(a), "l"(b)); return d;
}
__device__ __forceinline__ u64 add2(u64 a, u64 b) {
    u64 d; asm("add.rn.f32x2 %0, %1, %2;" : "=l"(d) : "l"(a), "l"(b)); return d;
}

struct Pairs { u64 tL, t0a, t0b, tm, tR; };

// Build the 5 packed tap operands for one input row held as float4/lane.
// Lanes >= 28 carry zeros; lane 0 (and lanes >= 28) force left halo to 0.
__device__ __forceinline__ Pairs mkpairs(float4 v, int lane) {
    float left  = __shfl_up_sync(0xFFFFFFFFu, v.w, 1);
    float right = __shfl_down_sync(0xFFFFFFFFu, v.x, 1);
    if (lane == 0 || lane >= 28) left = 0.f;
    Pairs p;
    p.tL  = pk(left, v.x);
    p.t0a = pk(v.x,  v.y);
    p.tm  = pk(v.y,  v.z);
    p.t0b = pk(v.z,  v.w);
    p.tR  = pk(v.w,  right);
    return p;
}

__device__ __forceinline__ void krow(u64& lo, u64& hi, const u64* kp, int kr, const Pairs& p) {
    lo = fma2(kp[3*kr+0], p.tL,  lo);
    lo = fma2(kp[3*kr+1], p.t0a, lo);
    lo = fma2(kp[3*kr+2], p.tm,  lo);
    hi = fma2(kp[3*kr+0], p.tm,  hi);
    hi = fma2(kp[3*kr+1], p.t0b, hi);
    hi = fma2(kp[3*kr+2], p.tR,  hi);
}
__device__ __forceinline__ void krow_init(u64& lo, u64& hi, const u64* kp, const Pairs& p) {
    lo = mul2(kp[0], p.tL);
    lo = fma2(kp[1], p.t0a, lo);
    lo = fma2(kp[2], p.tm,  lo);
    hi = mul2(kp[0], p.tm);
    hi = fma2(kp[1], p.t0b, hi);
    hi = fma2(kp[2], p.tR,  hi);
}

__device__ __forceinline__ float4 ldrow(const float* __restrict__ base, int r,
                                        int lane, bool active) {
    float4 t = make_float4(0.f, 0.f, 0.f, 0.f);
    if (active && (unsigned)r < HW)
        t = __ldg(reinterpret_cast<const float4*>(base + r * HW) + lane);
    return t;
}

// Pass 1: per-channel sums of conv and conv^2 (bias folded analytically later).
// One block = whole (n,c) image: 7 warps x 16-row strips.
__global__ void __launch_bounds__(224)
stats_kernel(const float* __restrict__ in, const float* __restrict__ w) {
    __shared__ float red1[7], red2[7];
    int lane = threadIdx.x & 31, wid = threadIdx.x >> 5;
    int c = blockIdx.x, n = blockIdx.y;
    int h0 = wid * STRIP;
    bool active = lane < 28;
    const float* base = in + (size_t)(n * CCH + c) * IMG;

    u64 kp[9];
    #pragma unroll
    for (int i = 0; i < 9; i++) { float kk = __ldg(w + c * 9 + i); kp[i] = pk(kk, kk); }

    float4 v[3];
    #pragma unroll
    for (int i = 0; i < 3; i++) v[i] = ldrow(base, h0 - 1 + i, lane, active);

    u64 alo[3], ahi[3];
    u64 s1lo = 0, s1hi = 0, s2lo = 0, s2hi = 0;

    #pragma unroll
    for (int rr = 0; rr < STRIP + 2; rr++) {
        float4 cur = v[rr % 3];
        if (rr < STRIP - 1) v[rr % 3] = ldrow(base, h0 + rr + 2, lane, active);
        Pairs p = mkpairs(cur, lane);
        if (rr >= 2) {                       // finish + emit output row h0+rr-2
            int es = (rr + 1) % 3;
            krow(alo[es], ahi[es], kp, 2, p);
            s1lo = add2(s1lo, alo[es]); s1hi = add2(s1hi, ahi[es]);
            s2lo = fma2(alo[es], alo[es], s2lo);
            s2hi = fma2(ahi[es], ahi[es], s2hi);
        }
        if (rr >= 1) { int ks = (rr + 2) % 3; krow(alo[ks], ahi[ks], kp, 1, p); }
        if (rr < STRIP) { int is = rr % 3; krow_init(alo[is], ahi[is], kp, p); }
    }

    float x0, x1, x2, x3;
    upk(s1lo, x0, x1); upk(s1hi, x2, x3);
    float s1 = (x0 + x1) + (x2 + x3);
    upk(s2lo, x0, x1); upk(s2hi, x2, x3);
    float s2 = (x0 + x1) + (x2 + x3);

    #pragma unroll
    for (int off = 16; off > 0; off >>= 1) {
        s1 += __shfl_down_sync(0xFFFFFFFFu, s1, off);
        s2 += __shfl_down_sync(0xFFFFFFFFu, s2, off);
    }
    if (lane == 0) { red1[wid] = s1; red2[wid] = s2; }
    __syncthreads();
    if (threadIdx.x == 0) {
        float t1 = 0.f, t2 = 0.f;
        #pragma unroll
        for (int i = 0; i < 7; i++) { t1 += red1[i]; t2 += red2[i]; }
        atomicAdd(&g_sum[c], t1);
        atomicAdd(&g_sumsq[c], t2);
    }
}

// Fold bias/mean/var/gamma/beta into per-channel scale & shift.
__global__ void finalize_kernel(const float* __restrict__ b,
                                const float* __restrict__ gamma,
                                const float* __restrict__ beta) {
    int c = threadIdx.x;
    if (c < CCH) {
        float bias  = b[c];
        float sum_y = g_sum[c] + NHW_F * bias;
        float ssq_y = g_sumsq[c] + 2.f * bias * g_sum[c] + NHW_F * bias * bias;
        float mean  = sum_y / NHW_F;
        float var   = ssq_y / NHW_F - mean * mean;
        float sc    = gamma[c] * rsqrtf(var + BN_EPS);
        g_scale[c] = sc;
        g_shift[c] = beta[c] + sc * (bias - mean);
    }
}

// Pass 2: recompute conv, apply folded scale/shift + ReLU6, write float4.
__global__ void __launch_bounds__(224)
output_kernel(const float* __restrict__ in, const float* __restrict__ w,
              float* __restrict__ out) {
    int lane = threadIdx.x & 31, wid = threadIdx.x >> 5;
    int c = blockIdx.x, n = blockIdx.y;
    int h0 = wid * STRIP;
    bool active = lane < 28;
    const float* base = in + (size_t)(n * CCH + c) * IMG;

    u64 kp[9];
    #pragma unroll
    for (int i = 0; i < 9; i++) { float kk = __ldg(w + c * 9 + i); kp[i] = pk(kk, kk); }
    float sc = g_scale[c], sh = g_shift[c];
    u64 scp = pk(sc, sc), shp = pk(sh, sh);

    float4 v[3];
    #pragma unroll
    for (int i = 0; i < 3; i++) v[i] = ldrow(base, h0 - 1 + i, lane, active);

    u64 alo[3], ahi[3];
    float* optr = out + (size_t)(n * CCH + c) * IMG + h0 * HW + lane * 4;

    #pragma unroll
    for (int rr = 0; rr < STRIP + 2; rr++) {
        float4 cur = v[rr % 3];
        if (rr < STRIP - 1) v[rr % 3] = ldrow(base, h0 + rr + 2, lane, active);
        Pairs p = mkpairs(cur, lane);
        if (rr >= 2) {                       // finish + store output row h0+rr-2
            int es = (rr + 1) % 3;
            krow(alo[es], ahi[es], kp, 2, p);
            u64 rlo = fma2(alo[es], scp, shp);
            u64 rhi = fma2(ahi[es], scp, shp);
            float x0, x1, x2, x3;
            upk(rlo, x0, x1); upk(rhi, x2, x3);
            float4 o;
            o.x = fminf(fmaxf(x0, 0.f), 6.f);
            o.y = fminf(fmaxf(x1, 0.f), 6.f);
            o.z = fminf(fmaxf(x2, 0.f), 6.f);
            o.w = fminf(fmaxf(x3, 0.f), 6.f);
            if (active) *reinterpret_cast<float4*>(optr) = o;
            optr += HW;
        }
        if (rr >= 1) { int ks = (rr + 2) % 3; krow(alo[ks], ahi[ks], kp, 1, p); }
        if (rr < STRIP) { int is = rr % 3; krow_init(alo[is], ahi[is], kp, p); }
    }
}

extern "C" void kernel_launch(void* const* d_in, const int* in_sizes, int n_in,
                              void* d_out, int out_size) {
    const float* in    = (const float*)d_in[0];
    const float* w     = (const float*)d_in[1];
    const float* b     = (const float*)d_in[2];
    const float* gamma = (const float*)d_in[3];
    const float* beta  = (const float*)d_in[4];
    float* out = (float*)d_out;

    dim3 grid(CCH, NB);   // 192 x 32 = 6144 blocks, one per (c, n) image
    zero_stats_kernel<<<1, CCH>>>();
    stats_kernel<<<grid, 224>>>(in, w);
    finalize_kernel<<<1, CCH>>>(b, gamma, beta);
    output_kernel<<<grid, 224>>>(in, w, out);
}